// round 5
// baseline (speedup 1.0000x reference)
#include <cuda_runtime.h>
#include <cstdint>
#include <cfloat>

#define NROW 32768
#define NCOL 1024
#define DIM 64
#define ITERS 100
#define SINK_BLOCKS 128
#define XQ_ELEMS (NROW * DIM)          // 2097152
#define LOSS_OFF XQ_ELEMS
#define IDX_OFF (XQ_ELEMS + 1)

// k_sink dynamic smem: sC[1024] | sacc[16*256] | sR[256] | sTrash[16] | sPC[48*1024]
#define NCACHE 3                        // cached rows per warp (48/block, 192KB)
#define SINK_SMEM_FLOATS (1024 + 16 * 256 + 256 + 16 + 48 * 1024)
#define SINK_SMEM_BYTES (SINK_SMEM_FLOATS * 4)   // 218176

// ---------------- device scratch (static: no runtime allocation) ----------------
__device__ float    g_P[(size_t)NROW * NCOL];     // d, then P' = exp(sc*(middle-d)); 134MB
__device__ float    g_xx[NROW];
__device__ float    g_ww[NCOL];
__device__ float    g_colsum[ITERS][NCOL];        // per-iteration column sums
__device__ int      g_idxQ[NROW];
__device__ int      g_idxD[NROW];
__device__ int      g_bad;
__device__ float    g_losspart[4096];
__device__ unsigned g_dmin_u, g_dmax_u;
__device__ float    g_middle, g_sc;
__device__ unsigned g_barrier;

__device__ __forceinline__ unsigned fmapu(float f) {
    unsigned u = __float_as_uint(f);
    return (u & 0x80000000u) ? ~u : (u | 0x80000000u);
}
__device__ __forceinline__ float funmap(unsigned m) {
    unsigned v = (m & 0x80000000u) ? (m & 0x7fffffffu) : ~m;
    return __uint_as_float(v);
}

// FFMA-only exp (no MUFU). Bit-identical to the R2/R4 passing kernels.
__device__ __forceinline__ float fexp(float x) {
    float t = x * 1.4426950408889634f;
    float r = rintf(t);
    float g = (t - r) * 0.6931471805599453f;
    float p = 1.0f + g * (1.0f + g * (0.5f + g * (0.16666666667f +
              g * (0.041666666667f + g * (0.0083333333333f + g * 0.0013888888889f)))));
    int ir = (int)r;
    float s = __int_as_float((ir + 127) << 23);
    return p * s;
}

// ---------------- 32-byte access helpers ----------------
struct F8 { float f[8]; };

__device__ __forceinline__ F8 ldg_evl8(const float* p) {   // keep in L2
    unsigned long long a, b, c, d;
    asm volatile("ld.global.nc.L2::evict_last.v4.b64 {%0,%1,%2,%3}, [%4];"
                 : "=l"(a), "=l"(b), "=l"(c), "=l"(d) : "l"(p));
    F8 r;
    r.f[0] = __uint_as_float((unsigned)a); r.f[1] = __uint_as_float((unsigned)(a >> 32));
    r.f[2] = __uint_as_float((unsigned)b); r.f[3] = __uint_as_float((unsigned)(b >> 32));
    r.f[4] = __uint_as_float((unsigned)c); r.f[5] = __uint_as_float((unsigned)(c >> 32));
    r.f[6] = __uint_as_float((unsigned)d); r.f[7] = __uint_as_float((unsigned)(d >> 32));
    return r;
}
__device__ __forceinline__ F8 ldg_cs8(const float* p) {    // stream through L2
    F8 r;
    float4 a = __ldcs((const float4*)p);
    float4 b = __ldcs((const float4*)p + 1);
    r.f[0] = a.x; r.f[1] = a.y; r.f[2] = a.z; r.f[3] = a.w;
    r.f[4] = b.x; r.f[5] = b.y; r.f[6] = b.z; r.f[7] = b.w;
    return r;
}
__device__ __forceinline__ F8 lds8(const float* p) {       // shared memory
    F8 r;
    float4 a = *(const float4*)p;
    float4 b = *(const float4*)(p + 4);
    r.f[0] = a.x; r.f[1] = a.y; r.f[2] = a.z; r.f[3] = a.w;
    r.f[4] = b.x; r.f[5] = b.y; r.f[6] = b.z; r.f[7] = b.w;
    return r;
}
__device__ __forceinline__ void stg_evl8(float* p, const F8& v) {
    unsigned long long a = (unsigned long long)__float_as_uint(v.f[0]) |
                           ((unsigned long long)__float_as_uint(v.f[1]) << 32);
    unsigned long long b = (unsigned long long)__float_as_uint(v.f[2]) |
                           ((unsigned long long)__float_as_uint(v.f[3]) << 32);
    unsigned long long c = (unsigned long long)__float_as_uint(v.f[4]) |
                           ((unsigned long long)__float_as_uint(v.f[5]) << 32);
    unsigned long long d = (unsigned long long)__float_as_uint(v.f[6]) |
                           ((unsigned long long)__float_as_uint(v.f[7]) << 32);
    asm volatile("st.global.L2::evict_last.v4.b64 [%0], {%1,%2,%3,%4};"
                 :: "l"(p), "l"(a), "l"(b), "l"(c), "l"(d) : "memory");
}
__device__ __forceinline__ void stg_cs8(float* p, const F8& v) {
    __stcs((float4*)p,     make_float4(v.f[0], v.f[1], v.f[2], v.f[3]));
    __stcs((float4*)p + 1, make_float4(v.f[4], v.f[5], v.f[6], v.f[7]));
}
__device__ __forceinline__ void sts8(float* p, const F8& v) {
    *(float4*)p       = make_float4(v.f[0], v.f[1], v.f[2], v.f[3]);
    *(float4*)(p + 4) = make_float4(v.f[4], v.f[5], v.f[6], v.f[7]);
}

// ---------------- init: norms (identical FP order to R4 k_norms) + colsum zero + scalars ----
__global__ void k_init0(const float* __restrict__ x, const float* __restrict__ W) {
    int tid = threadIdx.x;
    if (blockIdx.x < 4224) {
        int gw = blockIdx.x * 8 + (tid >> 5);
        int lane = tid & 31;
        if (gw >= NROW + NCOL) return;
        const float* src = (gw < NROW) ? (x + (size_t)gw * DIM)
                                       : (W + (size_t)(gw - NROW) * DIM);
        float2 v = ((const float2*)src)[lane];
        float s = v.x * v.x + v.y * v.y;
#pragma unroll
        for (int o = 16; o; o >>= 1) s += __shfl_xor_sync(0xffffffffu, s, o);
        if (lane == 0) {
            if (gw < NROW) g_xx[gw] = s;
            else           g_ww[gw - NROW] = s;
        }
    } else {
        int i = (blockIdx.x - 4224) * 256 + tid;
        if (i < ITERS * NCOL) ((float*)g_colsum)[i] = 0.0f;
        if (blockIdx.x == 4224 && tid == 0) {
            g_barrier = 0u;
            g_bad = 0;
            g_dmin_u = 0xFFFFFFFFu;
            g_dmax_u = 0u;
        }
    }
}

// ---------------- d = xx + ww - 2 x@W^T; global min/max of d (unchanged from R4) ----------
__global__ void __launch_bounds__(256) k_gemm(const float* __restrict__ x,
                                              const float* __restrict__ W) {
    __shared__ float xsT[64][68];
    __shared__ float wsT[64][68];
    int tid = threadIdx.x;
    int r0 = blockIdx.x * 64;
    int c0 = blockIdx.y * 64;

    for (int n = tid; n < 1024; n += 256) {
        int r = n >> 4, d4 = (n & 15) << 2;
        float4 v = *(const float4*)(x + (size_t)(r0 + r) * DIM + d4);
        xsT[d4 + 0][r] = v.x; xsT[d4 + 1][r] = v.y;
        xsT[d4 + 2][r] = v.z; xsT[d4 + 3][r] = v.w;
        float4 u = *(const float4*)(W + (size_t)(c0 + r) * DIM + d4);
        wsT[d4 + 0][r] = u.x; wsT[d4 + 1][r] = u.y;
        wsT[d4 + 2][r] = u.z; wsT[d4 + 3][r] = u.w;
    }
    __syncthreads();

    int tx = tid & 15, ty = tid >> 4;
    float acc[4][4];
#pragma unroll
    for (int i = 0; i < 4; ++i)
#pragma unroll
        for (int j = 0; j < 4; ++j) acc[i][j] = 0.0f;

#pragma unroll 8
    for (int d = 0; d < 64; ++d) {
        float4 a = *(const float4*)&xsT[d][ty * 4];
        float4 b = *(const float4*)&wsT[d][tx * 4];
        float av[4] = {a.x, a.y, a.z, a.w};
        float bv[4] = {b.x, b.y, b.z, b.w};
#pragma unroll
        for (int i = 0; i < 4; ++i)
#pragma unroll
            for (int j = 0; j < 4; ++j) acc[i][j] += av[i] * bv[j];
    }

    float mn = FLT_MAX, mx = -FLT_MAX;
#pragma unroll
    for (int i = 0; i < 4; ++i) {
        int row = r0 + ty * 4 + i;
        float xxv = g_xx[row];
        float dv[4];
#pragma unroll
        for (int j = 0; j < 4; ++j) {
            dv[j] = (xxv + g_ww[c0 + tx * 4 + j]) - 2.0f * acc[i][j];
            mn = fminf(mn, dv[j]);
            mx = fmaxf(mx, dv[j]);
        }
        *(float4*)(g_P + (size_t)row * NCOL + c0 + tx * 4) =
            make_float4(dv[0], dv[1], dv[2], dv[3]);
    }

    __shared__ float smn[256], smx[256];
    smn[tid] = mn; smx[tid] = mx;
    __syncthreads();
    for (int s = 128; s; s >>= 1) {
        if (tid < s) {
            smn[tid] = fminf(smn[tid], smn[tid + s]);
            smx[tid] = fmaxf(smx[tid], smx[tid + s]);
        }
        __syncthreads();
    }
    if (tid == 0) {
        atomicMin(&g_dmin_u, fmapu(smn[0]));
        atomicMax(&g_dmax_u, fmapu(smx[0]));
    }
}

__global__ void k_consts() {
    float mn = funmap(g_dmin_u);
    float mx = funmap(g_dmax_u);
    float middle = (mx + mn) * 0.5f;
    float amp = mx - middle + 1e-5f;
    g_middle = middle;
    g_sc = 1.0f / (amp * 0.05f);
}

// ---------------- persistent Sinkhorn: transform+iter0 fused, SMEM P-cache, 100 iters ------
// Per block: 256 rows; warp w owns rows [16w, 16w+16).
//   rr < 3        : cached in SMEM (48 rows/block = 192KB, written in pre-phase)
//   3 <= rr < 13  : pinned in L2 (evict_last; 160 rows/block = 80MB chip-wide)
//   rr >= 13      : streamed (evict-first/.cs; 48 rows/block = 24.6MB DRAM/iter)
__global__ void __launch_bounds__(512, 1) k_sink() {
    extern __shared__ float sm[];
    float* sC     = sm;                        // [1024]
    float* sacc   = sm + 1024;                 // [16][256] quarter-staged partials
    float* sR     = sm + 1024 + 16 * 256;      // [256] last-iter row factors
    float* sTrash = sR + 256;                  // [16] never-taken sink
    float* sPC    = sTrash + 16;               // [48][1024] cached P rows

    int tid = threadIdx.x, lane = tid & 31, w = tid >> 5;
    int r0 = blockIdx.x * 256;
    unsigned phase = 0;
    float mid = g_middle, sc = g_sc;

    F8 racc[4];
#pragma unroll
    for (int q = 0; q < 4; ++q)
#pragma unroll
        for (int e = 0; e < 8; ++e) racc[q].f[e] = 0.0f;

    // ---- pre-phase == iteration 0: read d, P'=fexp, store (smem/evl/cs), dot with C=1 ----
    for (int rr = 0; rr < 16; ++rr) {
        int row = r0 + w * 16 + rr;
        float* pr = g_P + (size_t)row * NCOL;
        F8 p[4];
#pragma unroll
        for (int q = 0; q < 4; ++q) {
            F8 v = ldg_cs8(pr + lane * 8 + 256 * q);
#pragma unroll
            for (int e = 0; e < 8; ++e) v.f[e] = fexp((mid - v.f[e]) * sc);
            p[q] = v;
        }
        if (rr < NCACHE) {
            float* dst = sPC + (size_t)(w * NCACHE + rr) * 1024 + lane * 8;
#pragma unroll
            for (int q = 0; q < 4; ++q) sts8(dst + 256 * q, p[q]);
        } else if (rr < NCACHE + 10) {
#pragma unroll
            for (int q = 0; q < 4; ++q) stg_evl8(pr + lane * 8 + 256 * q, p[q]);
        } else {
#pragma unroll
            for (int q = 0; q < 4; ++q) stg_cs8(pr + lane * 8 + 256 * q, p[q]);
        }
        float dot = 0.0f;
#pragma unroll
        for (int q = 0; q < 4; ++q) {
            dot += p[q].f[0] * 1.0f + p[q].f[1] * 1.0f + p[q].f[2] * 1.0f + p[q].f[3] * 1.0f
                 + p[q].f[4] * 1.0f + p[q].f[5] * 1.0f + p[q].f[6] * 1.0f + p[q].f[7] * 1.0f;
        }
#pragma unroll
        for (int o = 16; o; o >>= 1) dot += __shfl_xor_sync(0xffffffffu, dot, o);
        float R = 1.0f / (32768.0f * dot);
#pragma unroll
        for (int q = 0; q < 4; ++q)
#pragma unroll
            for (int e = 0; e < 8; ++e) racc[q].f[e] += R * p[q].f[e];
        if (lane == 0) sR[w * 16 + rr] = R;
    }

    // ---- shared iteration tail: quarter-staged colsum reduction + RED + barrier ----
    for (int t = 0; t < ITERS; ++t) {
        if (t > 0) {
            // row pass for iteration t (sC holds C^(t) from colsum[t-1])
#pragma unroll
            for (int q = 0; q < 4; ++q)
#pragma unroll
                for (int e = 0; e < 8; ++e) racc[q].f[e] = 0.0f;

            for (int rr = 0; rr < 16; ++rr) {
                int row = r0 + w * 16 + rr;
                const float* pr = g_P + (size_t)row * NCOL;
                F8 p[4];
                if (rr < NCACHE) {
                    const float* src = sPC + (size_t)(w * NCACHE + rr) * 1024 + lane * 8;
#pragma unroll
                    for (int q = 0; q < 4; ++q) p[q] = lds8(src + 256 * q);
                } else if (rr < NCACHE + 10) {
#pragma unroll
                    for (int q = 0; q < 4; ++q) p[q] = ldg_evl8(pr + lane * 8 + 256 * q);
                } else {
#pragma unroll
                    for (int q = 0; q < 4; ++q) p[q] = ldg_cs8(pr + lane * 8 + 256 * q);
                }
                float dot = 0.0f;
#pragma unroll
                for (int q = 0; q < 4; ++q) {
                    const float* cv = sC + lane * 8 + 256 * q;
                    float4 c0 = *(const float4*)cv;
                    float4 c1 = *(const float4*)(cv + 4);
                    dot += p[q].f[0] * c0.x + p[q].f[1] * c0.y + p[q].f[2] * c0.z + p[q].f[3] * c0.w
                         + p[q].f[4] * c1.x + p[q].f[5] * c1.y + p[q].f[6] * c1.z + p[q].f[7] * c1.w;
                }
#pragma unroll
                for (int o = 16; o; o >>= 1) dot += __shfl_xor_sync(0xffffffffu, dot, o);
                float R = 1.0f / (32768.0f * dot);
#pragma unroll
                for (int q = 0; q < 4; ++q)
#pragma unroll
                    for (int e = 0; e < 8; ++e) racc[q].f[e] += R * p[q].f[e];
                if (lane == 0) sR[w * 16 + rr] = R;
            }
        }

        // quarter-staged deterministic reduction (per-column order: ww = 0..15, as in R4)
        float dummy = 0.0f;
#pragma unroll
        for (int q = 0; q < 4; ++q) {
            __syncthreads();
            float* dst = sacc + w * 256 + lane * 8;
            *(float4*)dst       = make_float4(racc[q].f[0], racc[q].f[1], racc[q].f[2], racc[q].f[3]);
            *(float4*)(dst + 4) = make_float4(racc[q].f[4], racc[q].f[5], racc[q].f[6], racc[q].f[7]);
            __syncthreads();
            if (tid < 256) {
                float s = 0.0f;
#pragma unroll
                for (int ww = 0; ww < 16; ++ww) s += sacc[ww * 256 + tid];
                dummy += atomicAdd(&g_colsum[t][q * 256 + tid], s);
            }
        }
        // completion fence: atomicAdd returns consumed -> REDs performed at L2
        if (__float_as_uint(dummy) == 0x7F800123u) sTrash[w] = dummy;
        __syncthreads();
        if (tid == 0) {
            unsigned arrived = atomicAdd(&g_barrier, 1u) + 1u;
            phase += SINK_BLOCKS;
            if (arrived < phase) {
                while (*(volatile unsigned*)&g_barrier < phase) __nanosleep(32);
            }
        }
        __syncthreads();

        for (int j = tid; j < NCOL; j += 512)
            sC[j] = 1.0f / (1024.0f * __ldcg(&g_colsum[t][j]));
        __syncthreads();
    }

    // ---- fused final pass: argmax(P'*C_final), argmax(P') (== argmin d), finiteness ----
    for (int rr = 0; rr < 16; ++rr) {
        int row = r0 + w * 16 + rr;
        const float* pr = g_P + (size_t)row * NCOL;
        float rb = sR[w * 16 + rr] * 32768.0f;

        float bq = -FLT_MAX; int biq = 0;
        float bp = -FLT_MAX; int bip = 0;
        bool bad = false;
#pragma unroll
        for (int q = 0; q < 4; ++q) {
            F8 p;
            if (rr < NCACHE)
                p = lds8(sPC + (size_t)(w * NCACHE + rr) * 1024 + lane * 8 + 256 * q);
            else if (rr < NCACHE + 10)
                p = ldg_evl8(pr + lane * 8 + 256 * q);
            else
                p = ldg_cs8(pr + lane * 8 + 256 * q);
            const float* cv = sC + lane * 8 + 256 * q;
            int jb = lane * 8 + 256 * q;
#pragma unroll
            for (int e = 0; e < 8; ++e) {
                float qv = p.f[e] * cv[e];
                float full = qv * rb;
                if (!(fabsf(full) <= FLT_MAX)) bad = true;
                if (qv > bq) { bq = qv; biq = jb + e; }
                if (p.f[e] > bp) { bp = p.f[e]; bip = jb + e; }
            }
        }
#pragma unroll
        for (int o = 16; o; o >>= 1) {
            float ov = __shfl_xor_sync(0xffffffffu, bq, o);
            int   oi = __shfl_xor_sync(0xffffffffu, biq, o);
            if (ov > bq || (ov == bq && oi < biq)) { bq = ov; biq = oi; }
            ov = __shfl_xor_sync(0xffffffffu, bp, o);
            oi = __shfl_xor_sync(0xffffffffu, bip, o);
            if (ov > bp || (ov == bp && oi < bip)) { bp = ov; bip = oi; }
        }
        bool anybad = __any_sync(0xffffffffu, bad);
        if (lane == 0) {
            g_idxQ[row] = biq;
            g_idxD[row] = bip;
            if (anybad) atomicOr(&g_bad, 1);
        }
    }
}

// ---------------- output + loss (unchanged) ----------------
__global__ void k_output(const float* __restrict__ x, const float* __restrict__ W,
                         float* __restrict__ out) {
    __shared__ float spart[8];
    int tid = threadIdx.x, lane = tid & 31, w = tid >> 5;
    int row = blockIdx.x * 8 + w;
    int idx = g_bad ? g_idxD[row] : g_idxQ[row];

    float2 wv = ((const float2*)(W + (size_t)idx * DIM))[lane];
    float2 xv = ((const float2*)(x + (size_t)row * DIM))[lane];
    float dx = wv.x - xv.x, dy = wv.y - xv.y;
    float2 st = make_float2(xv.x + dx, xv.y + dy);
    ((float2*)(out + (size_t)row * DIM))[lane] = st;

    float s = dx * dx + dy * dy;
#pragma unroll
    for (int o = 16; o; o >>= 1) s += __shfl_xor_sync(0xffffffffu, s, o);
    if (lane == 0) {
        spart[w] = s;
        out[IDX_OFF + row] = (float)idx;
    }
    __syncthreads();
    if (tid == 0) {
        float t = 0.f;
#pragma unroll
        for (int i = 0; i < 8; ++i) t += spart[i];
        g_losspart[blockIdx.x] = t;
    }
}

__global__ void k_loss(float* __restrict__ out) {
    __shared__ float sp[512];
    int tid = threadIdx.x;
    float s = 0.f;
    for (int i = tid; i < 4096; i += 512) s += g_losspart[i];
    sp[tid] = s;
    __syncthreads();
    for (int o = 256; o; o >>= 1) {
        if (tid < o) sp[tid] += sp[tid + o];
        __syncthreads();
    }
    if (tid == 0) {
        float m = sp[0] / (float)XQ_ELEMS;
        out[LOSS_OFF] = m + 0.25f * m;
    }
}

extern "C" void kernel_launch(void* const* d_in, const int* in_sizes, int n_in,
                              void* d_out, int out_size) {
    const float* x = (const float*)d_in[0];
    const float* W = (const float*)d_in[1];
    float* out = (float*)d_out;

    static bool attr_set = false;
    if (!attr_set) {
        cudaFuncSetAttribute(k_sink, cudaFuncAttributeMaxDynamicSharedMemorySize,
                             SINK_SMEM_BYTES);
        attr_set = true;
    }

    k_init0<<<4624, 256>>>(x, W);
    k_gemm<<<dim3(512, 16), 256>>>(x, W);
    k_consts<<<1, 1>>>();
    k_sink<<<SINK_BLOCKS, 512, SINK_SMEM_BYTES>>>();
    k_output<<<4096, 256>>>(x, W, out);
    k_loss<<<1, 512>>>(out);
}

// round 7
// speedup vs baseline: 1.1363x; 1.1363x over previous
#include <cuda_runtime.h>
#include <cstdint>
#include <cfloat>

#define NROW 32768
#define NCOL 1024
#define DIM 64
#define ITERS 100
#define SINK_BLOCKS 128
#define XQ_ELEMS (NROW * DIM)          // 2097152
#define LOSS_OFF XQ_ELEMS
#define IDX_OFF (XQ_ELEMS + 1)

// k_sink dynamic smem: sC[1024] | sacc[16*1024] | sR[256] | sTrash[16]
#define SINK_SMEM_FLOATS (1024 + 16 * 1024 + 256 + 16)
#define SINK_SMEM_BYTES (SINK_SMEM_FLOATS * 4)   // 70720

// ---------------- device scratch (static: no runtime allocation) ----------------
__device__ float    g_P[(size_t)NROW * NCOL];     // d, then P' = exp(sc*(middle-d)); 134MB
__device__ float    g_xx[NROW];
__device__ float    g_ww[NCOL];
__device__ float    g_colsum[ITERS][NCOL];        // per-iteration column sums
__device__ int      g_idxQ[NROW];
__device__ int      g_idxD[NROW];
__device__ int      g_bad;
__device__ float    g_losspart[4096];
__device__ unsigned g_dmin_u, g_dmax_u;
__device__ float    g_middle, g_sc;
__device__ unsigned g_barrier;

__device__ __forceinline__ unsigned fmapu(float f) {
    unsigned u = __float_as_uint(f);
    return (u & 0x80000000u) ? ~u : (u | 0x80000000u);
}
__device__ __forceinline__ float funmap(unsigned m) {
    unsigned v = (m & 0x80000000u) ? (m & 0x7fffffffu) : ~m;
    return __uint_as_float(v);
}

// FFMA-only exp (no MUFU). Bit-identical to the R2/R4 passing kernels.
__device__ __forceinline__ float fexp(float x) {
    float t = x * 1.4426950408889634f;
    float r = rintf(t);
    float g = (t - r) * 0.6931471805599453f;
    float p = 1.0f + g * (1.0f + g * (0.5f + g * (0.16666666667f +
              g * (0.041666666667f + g * (0.0083333333333f + g * 0.0013888888889f)))));
    int ir = (int)r;
    float s = __int_as_float((ir + 127) << 23);
    return p * s;
}

// ---------------- 32-byte access helpers ----------------
struct F8 { float f[8]; };

__device__ __forceinline__ F8 ldg_evl8(const float* p) {   // keep in L2
    unsigned long long a, b, c, d;
    asm volatile("ld.global.nc.L2::evict_last.v4.b64 {%0,%1,%2,%3}, [%4];"
                 : "=l"(a), "=l"(b), "=l"(c), "=l"(d) : "l"(p));
    F8 r;
    r.f[0] = __uint_as_float((unsigned)a); r.f[1] = __uint_as_float((unsigned)(a >> 32));
    r.f[2] = __uint_as_float((unsigned)b); r.f[3] = __uint_as_float((unsigned)(b >> 32));
    r.f[4] = __uint_as_float((unsigned)c); r.f[5] = __uint_as_float((unsigned)(c >> 32));
    r.f[6] = __uint_as_float((unsigned)d); r.f[7] = __uint_as_float((unsigned)(d >> 32));
    return r;
}
__device__ __forceinline__ F8 ldg_cs8(const float* p) {    // stream through L2
    F8 r;
    float4 a = __ldcs((const float4*)p);
    float4 b = __ldcs((const float4*)p + 1);
    r.f[0] = a.x; r.f[1] = a.y; r.f[2] = a.z; r.f[3] = a.w;
    r.f[4] = b.x; r.f[5] = b.y; r.f[6] = b.z; r.f[7] = b.w;
    return r;
}
__device__ __forceinline__ void stg_evl8(float* p, const F8& v) {
    unsigned long long a = (unsigned long long)__float_as_uint(v.f[0]) |
                           ((unsigned long long)__float_as_uint(v.f[1]) << 32);
    unsigned long long b = (unsigned long long)__float_as_uint(v.f[2]) |
                           ((unsigned long long)__float_as_uint(v.f[3]) << 32);
    unsigned long long c = (unsigned long long)__float_as_uint(v.f[4]) |
                           ((unsigned long long)__float_as_uint(v.f[5]) << 32);
    unsigned long long d = (unsigned long long)__float_as_uint(v.f[6]) |
                           ((unsigned long long)__float_as_uint(v.f[7]) << 32);
    asm volatile("st.global.L2::evict_last.v4.b64 [%0], {%1,%2,%3,%4};"
                 :: "l"(p), "l"(a), "l"(b), "l"(c), "l"(d) : "memory");
}
__device__ __forceinline__ void stg_cs8(float* p, const F8& v) {
    __stcs((float4*)p,     make_float4(v.f[0], v.f[1], v.f[2], v.f[3]));
    __stcs((float4*)p + 1, make_float4(v.f[4], v.f[5], v.f[6], v.f[7]));
}

// ---------------- init: norms (identical FP order) + colsum zero + scalars ----------------
__global__ void k_init0(const float* __restrict__ x, const float* __restrict__ W) {
    int tid = threadIdx.x;
    if (blockIdx.x < 4224) {
        int gw = blockIdx.x * 8 + (tid >> 5);
        int lane = tid & 31;
        if (gw >= NROW + NCOL) return;
        const float* src = (gw < NROW) ? (x + (size_t)gw * DIM)
                                       : (W + (size_t)(gw - NROW) * DIM);
        float2 v = ((const float2*)src)[lane];
        float s = v.x * v.x + v.y * v.y;
#pragma unroll
        for (int o = 16; o; o >>= 1) s += __shfl_xor_sync(0xffffffffu, s, o);
        if (lane == 0) {
            if (gw < NROW) g_xx[gw] = s;
            else           g_ww[gw - NROW] = s;
        }
    } else {
        int i = (blockIdx.x - 4224) * 256 + tid;
        if (i < ITERS * NCOL) ((float*)g_colsum)[i] = 0.0f;
        if (blockIdx.x == 4224 && tid == 0) {
            g_barrier = 0u;
            g_bad = 0;
            g_dmin_u = 0xFFFFFFFFu;
            g_dmax_u = 0u;
        }
    }
}

// ---------------- d = xx + ww - 2 x@W^T; global min/max of d ----------------
__global__ void __launch_bounds__(256) k_gemm(const float* __restrict__ x,
                                              const float* __restrict__ W) {
    __shared__ float xsT[64][68];
    __shared__ float wsT[64][68];
    int tid = threadIdx.x;
    int r0 = blockIdx.x * 64;
    int c0 = blockIdx.y * 64;

    for (int n = tid; n < 1024; n += 256) {
        int r = n >> 4, d4 = (n & 15) << 2;
        float4 v = *(const float4*)(x + (size_t)(r0 + r) * DIM + d4);
        xsT[d4 + 0][r] = v.x; xsT[d4 + 1][r] = v.y;
        xsT[d4 + 2][r] = v.z; xsT[d4 + 3][r] = v.w;
        float4 u = *(const float4*)(W + (size_t)(c0 + r) * DIM + d4);
        wsT[d4 + 0][r] = u.x; wsT[d4 + 1][r] = u.y;
        wsT[d4 + 2][r] = u.z; wsT[d4 + 3][r] = u.w;
    }
    __syncthreads();

    int tx = tid & 15, ty = tid >> 4;
    float acc[4][4];
#pragma unroll
    for (int i = 0; i < 4; ++i)
#pragma unroll
        for (int j = 0; j < 4; ++j) acc[i][j] = 0.0f;

#pragma unroll 8
    for (int d = 0; d < 64; ++d) {
        float4 a = *(const float4*)&xsT[d][ty * 4];
        float4 b = *(const float4*)&wsT[d][tx * 4];
        float av[4] = {a.x, a.y, a.z, a.w};
        float bv[4] = {b.x, b.y, b.z, b.w};
#pragma unroll
        for (int i = 0; i < 4; ++i)
#pragma unroll
            for (int j = 0; j < 4; ++j) acc[i][j] += av[i] * bv[j];
    }

    float mn = FLT_MAX, mx = -FLT_MAX;
#pragma unroll
    for (int i = 0; i < 4; ++i) {
        int row = r0 + ty * 4 + i;
        float xxv = g_xx[row];
        float dv[4];
#pragma unroll
        for (int j = 0; j < 4; ++j) {
            dv[j] = (xxv + g_ww[c0 + tx * 4 + j]) - 2.0f * acc[i][j];
            mn = fminf(mn, dv[j]);
            mx = fmaxf(mx, dv[j]);
        }
        *(float4*)(g_P + (size_t)row * NCOL + c0 + tx * 4) =
            make_float4(dv[0], dv[1], dv[2], dv[3]);
    }

    __shared__ float smn[256], smx[256];
    smn[tid] = mn; smx[tid] = mx;
    __syncthreads();
    for (int s = 128; s; s >>= 1) {
        if (tid < s) {
            smn[tid] = fminf(smn[tid], smn[tid + s]);
            smx[tid] = fmaxf(smx[tid], smx[tid + s]);
        }
        __syncthreads();
    }
    if (tid == 0) {
        atomicMin(&g_dmin_u, fmapu(smn[0]));
        atomicMax(&g_dmax_u, fmapu(smx[0]));
    }
}

__global__ void k_consts() {
    float mn = funmap(g_dmin_u);
    float mx = funmap(g_dmax_u);
    float middle = (mx + mn) * 0.5f;
    float amp = mx - middle + 1e-5f;
    g_middle = middle;
    g_sc = 1.0f / (amp * 0.05f);
}

// ---------------- persistent Sinkhorn ----------------
// Block owns 256 contiguous rows; warp w owns rows [16w, 16w+16).
//   (row mod 16) < 11 : pinned in L2 (evict_last, 88MB chip-wide)
//   else              : streamed (.cs, 46MB DRAM/iter)
// Hot loop processes rows in PAIRS: 8 loads in flight, 2 interleaved shuffle chains.
// All per-row FP orderings identical to the R4 passing kernel.
__global__ void __launch_bounds__(512, 1) k_sink() {
    extern __shared__ float sm[];
    float* sC     = sm;                      // [1024]
    float* sacc   = sm + 1024;               // [16][1024] per-warp column partials
    float* sR     = sm + 1024 + 16 * 1024;   // [256] last-iter row factors
    float* sTrash = sR + 256;                // [16] never-taken sink

    int tid = threadIdx.x, lane = tid & 31, w = tid >> 5;
    int r0 = blockIdx.x * 256;
    unsigned phase = 0;
    float mid = g_middle, sc = g_sc;

    F8 racc[4];
#pragma unroll
    for (int q = 0; q < 4; ++q)
#pragma unroll
        for (int e = 0; e < 8; ++e) racc[q].f[e] = 0.0f;

    // ---- pre-phase == transform + iteration 0 (C=1): read d, P'=fexp, store, dot ----
#pragma unroll
    for (int rr = 0; rr < 16; ++rr) {
        int row = r0 + w * 16 + rr;
        float* pr = g_P + (size_t)row * NCOL;
        F8 p[4];
#pragma unroll
        for (int q = 0; q < 4; ++q) {
            F8 v = ldg_cs8(pr + lane * 8 + 256 * q);
#pragma unroll
            for (int e = 0; e < 8; ++e) v.f[e] = fexp((mid - v.f[e]) * sc);
            p[q] = v;
        }
        if (rr < 11) {
#pragma unroll
            for (int q = 0; q < 4; ++q) stg_evl8(pr + lane * 8 + 256 * q, p[q]);
        } else {
#pragma unroll
            for (int q = 0; q < 4; ++q) stg_cs8(pr + lane * 8 + 256 * q, p[q]);
        }
        float dot = 0.0f;
#pragma unroll
        for (int q = 0; q < 4; ++q) {
            dot += p[q].f[0] * 1.0f + p[q].f[1] * 1.0f + p[q].f[2] * 1.0f + p[q].f[3] * 1.0f
                 + p[q].f[4] * 1.0f + p[q].f[5] * 1.0f + p[q].f[6] * 1.0f + p[q].f[7] * 1.0f;
        }
#pragma unroll
        for (int o = 16; o; o >>= 1) dot += __shfl_xor_sync(0xffffffffu, dot, o);
        float R = 1.0f / (32768.0f * dot);
#pragma unroll
        for (int q = 0; q < 4; ++q)
#pragma unroll
            for (int e = 0; e < 8; ++e) racc[q].f[e] += R * p[q].f[e];
        if (lane == 0) sR[w * 16 + rr] = R;
    }

    // ---- iterations; t==0 uses the pre-phase racc ----
    for (int t = 0; t < ITERS; ++t) {
        if (t > 0) {
#pragma unroll
            for (int q = 0; q < 4; ++q)
#pragma unroll
                for (int e = 0; e < 8; ++e) racc[q].f[e] = 0.0f;

#pragma unroll
            for (int rp = 0; rp < 8; ++rp) {            // row PAIRS (2*rp, 2*rp+1)
                int ra = r0 + w * 16 + 2 * rp;
                const float* pa = g_P + (size_t)ra * NCOL;
                const float* pb = pa + NCOL;
                F8 A[4], B[4];
                // interleaved loads: 8 requests in flight before any consumption
#pragma unroll
                for (int q = 0; q < 4; ++q) {
                    if (2 * rp < 11)     A[q] = ldg_evl8(pa + lane * 8 + 256 * q);
                    else                 A[q] = ldg_cs8(pa + lane * 8 + 256 * q);
                    if (2 * rp + 1 < 11) B[q] = ldg_evl8(pb + lane * 8 + 256 * q);
                    else                 B[q] = ldg_cs8(pb + lane * 8 + 256 * q);
                }
                float dota = 0.0f, dotb = 0.0f;
#pragma unroll
                for (int q = 0; q < 4; ++q) {
                    const float* cv = sC + lane * 8 + 256 * q;
                    float4 c0 = *(const float4*)cv;
                    float4 c1 = *(const float4*)(cv + 4);
                    dota += A[q].f[0] * c0.x + A[q].f[1] * c0.y + A[q].f[2] * c0.z + A[q].f[3] * c0.w
                          + A[q].f[4] * c1.x + A[q].f[5] * c1.y + A[q].f[6] * c1.z + A[q].f[7] * c1.w;
                    dotb += B[q].f[0] * c0.x + B[q].f[1] * c0.y + B[q].f[2] * c0.z + B[q].f[3] * c0.w
                          + B[q].f[4] * c1.x + B[q].f[5] * c1.y + B[q].f[6] * c1.z + B[q].f[7] * c1.w;
                }
                // two independent shuffle chains, interleaved
#pragma unroll
                for (int o = 16; o; o >>= 1) {
                    dota += __shfl_xor_sync(0xffffffffu, dota, o);
                    dotb += __shfl_xor_sync(0xffffffffu, dotb, o);
                }
                float Ra = 1.0f / (32768.0f * dota);
                float Rb = 1.0f / (32768.0f * dotb);
                // racc: row a fully, then row b -> identical order to sequential rows
#pragma unroll
                for (int q = 0; q < 4; ++q)
#pragma unroll
                    for (int e = 0; e < 8; ++e) racc[q].f[e] += Ra * A[q].f[e];
#pragma unroll
                for (int q = 0; q < 4; ++q)
#pragma unroll
                    for (int e = 0; e < 8; ++e) racc[q].f[e] += Rb * B[q].f[e];
                if (lane == 0) {
                    sR[w * 16 + 2 * rp]     = Ra;
                    sR[w * 16 + 2 * rp + 1] = Rb;
                }
            }
        }

        // deterministic staged reduction: warp partials -> smem -> global RED
#pragma unroll
        for (int q = 0; q < 4; ++q) {
            float* dst = sacc + w * NCOL + lane * 8 + 256 * q;
            *(float4*)dst       = make_float4(racc[q].f[0], racc[q].f[1], racc[q].f[2], racc[q].f[3]);
            *(float4*)(dst + 4) = make_float4(racc[q].f[4], racc[q].f[5], racc[q].f[6], racc[q].f[7]);
        }
        __syncthreads();
        float dummy = 0.0f;
        for (int j = tid; j < NCOL; j += 512) {
            float s = 0.0f;
#pragma unroll
            for (int ww = 0; ww < 16; ++ww) s += sacc[ww * NCOL + j];
            dummy += atomicAdd(&g_colsum[t][j], s);
        }
        // completion fence: consuming atomic returns guarantees REDs performed at L2
        if (__float_as_uint(dummy) == 0x7F800123u) sTrash[w] = dummy;
        __syncthreads();
        if (tid == 0) {
            unsigned arrived = atomicAdd(&g_barrier, 1u) + 1u;
            phase += SINK_BLOCKS;
            if (arrived < phase) {
                while (*(volatile unsigned*)&g_barrier < phase) __nanosleep(32);
            }
        }
        __syncthreads();

        for (int j = tid; j < NCOL; j += 512)
            sC[j] = 1.0f / (1024.0f * __ldcg(&g_colsum[t][j]));
        __syncthreads();
    }

    // ---- fused final pass: argmax(P'*C_final), argmax(P') (== argmin d), finiteness ----
#pragma unroll
    for (int rr = 0; rr < 16; ++rr) {
        int row = r0 + w * 16 + rr;
        const float* pr = g_P + (size_t)row * NCOL;
        float rb = sR[w * 16 + rr] * 32768.0f;

        float bq = -FLT_MAX; int biq = 0;
        float bp = -FLT_MAX; int bip = 0;
        bool bad = false;
#pragma unroll
        for (int q = 0; q < 4; ++q) {
            F8 p = (rr < 11) ? ldg_evl8(pr + lane * 8 + 256 * q)
                             : ldg_cs8(pr + lane * 8 + 256 * q);
            const float* cv = sC + lane * 8 + 256 * q;
            int jb = lane * 8 + 256 * q;
#pragma unroll
            for (int e = 0; e < 8; ++e) {
                float qv = p.f[e] * cv[e];
                float full = qv * rb;
                if (!(fabsf(full) <= FLT_MAX)) bad = true;
                if (qv > bq) { bq = qv; biq = jb + e; }
                if (p.f[e] > bp) { bp = p.f[e]; bip = jb + e; }
            }
        }
#pragma unroll
        for (int o = 16; o; o >>= 1) {
            float ov = __shfl_xor_sync(0xffffffffu, bq, o);
            int   oi = __shfl_xor_sync(0xffffffffu, biq, o);
            if (ov > bq || (ov == bq && oi < biq)) { bq = ov; biq = oi; }
            ov = __shfl_xor_sync(0xffffffffu, bp, o);
            oi = __shfl_xor_sync(0xffffffffu, bip, o);
            if (ov > bp || (ov == bp && oi < bip)) { bp = ov; bip = oi; }
        }
        bool anybad = __any_sync(0xffffffffu, bad);
        if (lane == 0) {
            g_idxQ[row] = biq;
            g_idxD[row] = bip;
            if (anybad) atomicOr(&g_bad, 1);
        }
    }
}

// ---------------- output + loss ----------------
__global__ void k_output(const float* __restrict__ x, const float* __restrict__ W,
                         float* __restrict__ out) {
    __shared__ float spart[8];
    int tid = threadIdx.x, lane = tid & 31, w = tid >> 5;
    int row = blockIdx.x * 8 + w;
    int idx = g_bad ? g_idxD[row] : g_idxQ[row];

    float2 wv = ((const float2*)(W + (size_t)idx * DIM))[lane];
    float2 xv = ((const float2*)(x + (size_t)row * DIM))[lane];
    float dx = wv.x - xv.x, dy = wv.y - xv.y;
    float2 st = make_float2(xv.x + dx, xv.y + dy);
    ((float2*)(out + (size_t)row * DIM))[lane] = st;

    float s = dx * dx + dy * dy;
#pragma unroll
    for (int o = 16; o; o >>= 1) s += __shfl_xor_sync(0xffffffffu, s, o);
    if (lane == 0) {
        spart[w] = s;
        out[IDX_OFF + row] = (float)idx;
    }
    __syncthreads();
    if (tid == 0) {
        float t = 0.f;
#pragma unroll
        for (int i = 0; i < 8; ++i) t += spart[i];
        g_losspart[blockIdx.x] = t;
    }
}

__global__ void k_loss(float* __restrict__ out) {
    __shared__ float sp[512];
    int tid = threadIdx.x;
    float s = 0.f;
    for (int i = tid; i < 4096; i += 512) s += g_losspart[i];
    sp[tid] = s;
    __syncthreads();
    for (int o = 256; o; o >>= 1) {
        if (tid < o) sp[tid] += sp[tid + o];
        __syncthreads();
    }
    if (tid == 0) {
        float m = sp[0] / (float)XQ_ELEMS;
        out[LOSS_OFF] = m + 0.25f * m;
    }
}

extern "C" void kernel_launch(void* const* d_in, const int* in_sizes, int n_in,
                              void* d_out, int out_size) {
    const float* x = (const float*)d_in[0];
    const float* W = (const float*)d_in[1];
    float* out = (float*)d_out;

    static bool attr_set = false;
    if (!attr_set) {
        cudaFuncSetAttribute(k_sink, cudaFuncAttributeMaxDynamicSharedMemorySize,
                             SINK_SMEM_BYTES);
        attr_set = true;
    }

    k_init0<<<4624, 256>>>(x, W);
    k_gemm<<<dim3(512, 16), 256>>>(x, W);
    k_consts<<<1, 1>>>();
    k_sink<<<SINK_BLOCKS, 512, SINK_SMEM_BYTES>>>();
    k_output<<<4096, 256>>>(x, W, out);
    k_loss<<<1, 512>>>(out);
}